// round 8
// baseline (speedup 1.0000x reference)
#include <cuda_runtime.h>

#define NN 50000
#define NE 600000
#define IND 64
#define HID 128
#define NR 10
#define NL 6
#define NG 64

typedef unsigned long long ull;

// ---------------- device scratch (no allocs allowed) ----------------
__device__ float g_h0[NN * HID];
__device__ float g_h1[NN * HID];
__device__ float g_ob[NN * HID];
__device__ float g_agg[NN * NR * HID];   // 256 MB: per-node [r][dim] means
__device__ int g_deg[NN];
__device__ int g_off[NN + 1];
__device__ int g_cursor[NN];
__device__ unsigned g_edge[NE];          // (type<<16) | src

// ---------------- packed f32x2 helpers (FFMA2 path) ----------------
__device__ __forceinline__ ull fma2(ull a, ull b, ull c) {
    ull d;
    asm("fma.rn.f32x2 %0, %1, %2, %3;" : "=l"(d) : "l"(a), "l"(b), "l"(c));
    return d;
}
__device__ __forceinline__ ull dup2(float v) {
    ull d;
    asm("mov.b64 %0, {%1, %1};" : "=l"(d) : "f"(v));
    return d;
}
__device__ __forceinline__ ull pk2(float lo, float hi) {
    ull d;
    asm("mov.b64 %0, {%1, %2};" : "=l"(d) : "f"(lo), "f"(hi));
    return d;
}
__device__ __forceinline__ float2 unpk(ull v) {
    float lo, hi;
    asm("mov.b64 {%0, %1}, %2;" : "=f"(lo), "=f"(hi) : "l"(v));
    return make_float2(lo, hi);
}

// ---------------- CSR build ----------------
__global__ void k_zero_csr() {
    for (int i = blockIdx.x * blockDim.x + threadIdx.x; i < NN;
         i += gridDim.x * blockDim.x) {
        g_deg[i] = 0;
        g_cursor[i] = 0;
    }
}

__global__ void k_count(const int* __restrict__ eidx) {
    int e = blockIdx.x * blockDim.x + threadIdx.x;
    if (e < NE) atomicAdd(&g_deg[eidx[NE + e]], 1);
}

__global__ void k_scan() {
    __shared__ int part[1024];
    const int CH = (NN + 1023) / 1024;  // 49
    int t = threadIdx.x;
    int st = t * CH;
    int s = 0;
    for (int i = 0; i < CH; i++) {
        int idx = st + i;
        if (idx < NN) s += g_deg[idx];
    }
    part[t] = s;
    __syncthreads();
    for (int off = 1; off < 1024; off <<= 1) {
        int v = (t >= off) ? part[t - off] : 0;
        __syncthreads();
        part[t] += v;
        __syncthreads();
    }
    int run = part[t] - s;  // exclusive prefix for this chunk
    for (int i = 0; i < CH; i++) {
        int idx = st + i;
        if (idx < NN) {
            g_off[idx] = run;
            run += g_deg[idx];
        }
    }
    if (t == 1023) g_off[NN] = part[1023];
}

__global__ void k_fill(const int* __restrict__ eidx, const int* __restrict__ et) {
    int e = blockIdx.x * blockDim.x + threadIdx.x;
    if (e < NE) {
        int dst = eidx[NE + e];
        int pos = g_off[dst] + atomicAdd(&g_cursor[dst], 1);
        g_edge[pos] = ((unsigned)et[e] << 16) | (unsigned)eidx[e];
    }
}

// ---------------- SGEMM: C[M,128] = A[M,K] @ B[K,128] (+bias | +=C) ----------------
// 128x128 tile, BK=32, 256 threads, 8x8 micro-tile, packed f32x2 FMAs.
__global__ __launch_bounds__(256) void k_gemm(const float* __restrict__ A,
                                              const float* __restrict__ B,
                                              const float* __restrict__ bias,
                                              float* __restrict__ C, int M, int K,
                                              int accum) {
    __shared__ float As[32][132];  // [k][m], padded (4-float aligned rows)
    __shared__ float Bs[32][128];  // [k][n]
    int tid = threadIdx.x;
    int tx = tid & 15;   // n dir (8 cols each)
    int ty = tid >> 4;   // m dir (8 rows each)
    int row0 = blockIdx.x << 7;

    ull acc[8][4];
#pragma unroll
    for (int m = 0; m < 8; m++)
#pragma unroll
        for (int p = 0; p < 4; p++) acc[m][p] = 0ull;

    for (int k0 = 0; k0 < K; k0 += 32) {
#pragma unroll
        for (int it = 0; it < 4; it++) {
            int id = tid + (it << 8);      // 0..1023
            int m = id >> 3;               // 0..127
            int k4 = (id & 7) << 2;        // 0..28
            int gr = row0 + m;
            float4 v = make_float4(0.f, 0.f, 0.f, 0.f);
            if (gr < M) v = *(const float4*)(A + (size_t)gr * K + k0 + k4);
            As[k4 + 0][m] = v.x;
            As[k4 + 1][m] = v.y;
            As[k4 + 2][m] = v.z;
            As[k4 + 3][m] = v.w;
            int kb = id >> 5;              // 0..31
            int n4 = (id & 31) << 2;       // 0..124
            *(float4*)(&Bs[kb][n4]) =
                *(const float4*)(B + (size_t)(k0 + kb) * HID + n4);
        }
        __syncthreads();
#pragma unroll 8
        for (int k = 0; k < 32; k++) {
            float4 a0 = *(const float4*)(&As[k][ty << 3]);
            float4 a1 = *(const float4*)(&As[k][(ty << 3) + 4]);
            float4 b0 = *(const float4*)(&Bs[k][tx << 3]);
            float4 b1 = *(const float4*)(&Bs[k][(tx << 3) + 4]);
            ull bp_[4] = {pk2(b0.x, b0.y), pk2(b0.z, b0.w), pk2(b1.x, b1.y),
                          pk2(b1.z, b1.w)};
            float av[8] = {a0.x, a0.y, a0.z, a0.w, a1.x, a1.y, a1.z, a1.w};
#pragma unroll
            for (int m = 0; m < 8; m++) {
                ull ad = dup2(av[m]);
#pragma unroll
                for (int p = 0; p < 4; p++) acc[m][p] = fma2(ad, bp_[p], acc[m][p]);
            }
        }
        __syncthreads();
    }

#pragma unroll
    for (int m = 0; m < 8; m++) {
        int gr = row0 + (ty << 3) + m;
        if (gr < M) {
            float2* cp = (float2*)(C + (size_t)gr * HID + (tx << 3));
#pragma unroll
            for (int p = 0; p < 4; p++) {
                float2 v = unpk(acc[m][p]);
                if (accum) {
                    float2 o = cp[p];
                    v.x += o.x;
                    v.y += o.y;
                } else if (bias) {
                    v.x += bias[(tx << 3) + 2 * p];
                    v.y += bias[(tx << 3) + 2 * p + 1];
                }
                cp[p] = v;
            }
        }
    }
}

// ---------------- per-node relation-mean aggregation (warp/node, no atomics) ------
__global__ __launch_bounds__(256) void k_agg(const float* __restrict__ h) {
    __shared__ float acc[8][NR][HID];  // 40 KB
    __shared__ int cnt[8][NR];
    int w = threadIdx.x >> 5, lane = threadIdx.x & 31;
    int node = (blockIdx.x << 3) + w;  // NN divisible by 8
#pragma unroll
    for (int r = 0; r < NR; r++)
        *(float4*)(&acc[w][r][lane << 2]) = make_float4(0.f, 0.f, 0.f, 0.f);
    if (lane < NR) cnt[w][lane] = 0;
    __syncwarp();

    int beg = g_off[node], end = g_off[node + 1];
    for (int e = beg; e < end; e++) {
        unsigned p = g_edge[e];
        int src = p & 0xFFFF;
        int r = p >> 16;
        float4 v = *(const float4*)(h + ((size_t)src << 7) + (lane << 2));
        float4 a = *(float4*)(&acc[w][r][lane << 2]);
        a.x += v.x;
        a.y += v.y;
        a.z += v.z;
        a.w += v.w;
        *(float4*)(&acc[w][r][lane << 2]) = a;
        if (lane == 0) cnt[w][r]++;
    }
    __syncwarp();

    float* dst = g_agg + (size_t)node * (NR * HID);
#pragma unroll
    for (int r = 0; r < NR; r++) {
        int c = cnt[w][r];
        float s = (c > 0) ? 1.0f / (float)c : 0.0f;
        float4 a = *(float4*)(&acc[w][r][lane << 2]);
        a.x *= s;
        a.y *= s;
        a.z *= s;
        a.w *= s;
        *(float4*)(dst + r * HID + (lane << 2)) = a;
    }
}

// ---------------- LN + relu + residual epilogue (warp/node) ----------------
__global__ __launch_bounds__(256) void k_ln(const float* __restrict__ conv,
                                            const float* __restrict__ hres,
                                            const float* __restrict__ gam,
                                            const float* __restrict__ bet,
                                            float* __restrict__ hout) {
    int w = threadIdx.x >> 5, lane = threadIdx.x & 31;
    int node = (blockIdx.x << 3) + w;
    if (node >= NN) return;
    float4 v = *(const float4*)(conv + ((size_t)node << 7) + (lane << 2));
    float s = v.x + v.y + v.z + v.w;
#pragma unroll
    for (int o = 16; o > 0; o >>= 1) s += __shfl_xor_sync(0xffffffffu, s, o);
    float mu = s * (1.0f / 128.0f);
    float dx = v.x - mu, dy = v.y - mu, dz = v.z - mu, dw = v.w - mu;
    float q = dx * dx + dy * dy + dz * dz + dw * dw;
#pragma unroll
    for (int o = 16; o > 0; o >>= 1) q += __shfl_xor_sync(0xffffffffu, q, o);
    float inv = rsqrtf(q * (1.0f / 128.0f) + 1e-5f);
    float4 g4 = *(const float4*)(gam + (lane << 2));
    float4 b4 = *(const float4*)(bet + (lane << 2));
    float4 r4 = *(const float4*)(hres + ((size_t)node << 7) + (lane << 2));
    float4 o4;
    o4.x = fmaxf(dx * inv * g4.x + b4.x, 0.f) + r4.x;
    o4.y = fmaxf(dy * inv * g4.y + b4.y, 0.f) + r4.y;
    o4.z = fmaxf(dz * inv * g4.z + b4.z, 0.f) + r4.z;
    o4.w = fmaxf(dw * inv * g4.w + b4.w, 0.f) + r4.w;
    *(float4*)(hout + ((size_t)node << 7) + (lane << 2)) = o4;
}

// ---------------- output pooling ----------------
__global__ void k_zero_out(float* out) {
    int i = blockIdx.x * blockDim.x + threadIdx.x;
    if (i < NG * HID) out[i] = 0.f;
}

__global__ void k_pool(const float* __restrict__ h, const int* __restrict__ batch,
                       float* __restrict__ out) {
    int n0 = blockIdx.x * 512;
    if (n0 >= NN) return;
    int d = threadIdx.x;  // 128 threads = dims
    int end = n0 + 512;
    if (end > NN) end = NN;
    int g = batch[n0];
    float s = 0.f;
    for (int n = n0; n < end; n++) {
        int gb = batch[n];
        if (gb != g) {
            atomicAdd(&out[g * HID + d], s);
            s = 0.f;
            g = gb;
        }
        s += h[((size_t)n << 7) + d];
    }
    atomicAdd(&out[g * HID + d], s);
}

// ---------------- launcher ----------------
extern "C" void kernel_launch(void* const* d_in, const int* in_sizes, int n_in,
                              void* d_out, int out_size) {
    const float* x = (const float*)d_in[0];
    const int* eidx = (const int*)d_in[1];
    const int* etype = (const int*)d_in[2];
    const int* batch = (const int*)d_in[3];
    const float* Wp = (const float*)d_in[4];
    const float* bp = (const float*)d_in[5];
    const float* rel_w = (const float*)d_in[6];
    const float* root_w = (const float*)d_in[7];
    const float* conv_b = (const float*)d_in[8];
    const float* ln_g = (const float*)d_in[9];
    const float* ln_b = (const float*)d_in[10];
    float* out = (float*)d_out;

    float *h0, *h1, *ob, *agg;
    cudaGetSymbolAddress((void**)&h0, g_h0);
    cudaGetSymbolAddress((void**)&h1, g_h1);
    cudaGetSymbolAddress((void**)&ob, g_ob);
    cudaGetSymbolAddress((void**)&agg, g_agg);

    // CSR build (deterministic up to fp-insignificant edge ordering)
    k_zero_csr<<<64, 256>>>();
    k_count<<<(NE + 255) / 256, 256>>>(eidx);
    k_scan<<<1, 1024>>>();
    k_fill<<<(NE + 255) / 256, 256>>>(eidx, etype);

    // input projection: h0 = x @ Wp + bp
    k_gemm<<<(NN + 127) / 128, 256>>>(x, Wp, bp, h0, NN, IND, 0);

    float* hc = h0;
    float* hn = h1;
    for (int l = 0; l < NL; l++) {
        k_agg<<<NN / 8, 256>>>(hc);
        k_gemm<<<(NN + 127) / 128, 256>>>(hc, root_w + (size_t)l * HID * HID,
                                          conv_b + (size_t)l * HID, ob, NN, HID, 0);
        k_gemm<<<(NN + 127) / 128, 256>>>(agg, rel_w + (size_t)l * NR * HID * HID,
                                          (const float*)0, ob, NN, NR * HID, 1);
        k_ln<<<NN / 8, 256>>>(ob, hc, ln_g + (size_t)l * HID,
                              ln_b + (size_t)l * HID, hn);
        float* t = hc;
        hc = hn;
        hn = t;
    }

    k_zero_out<<<(NG * HID + 255) / 256, 256>>>(out);
    k_pool<<<(NN + 511) / 512, 128>>>(hc, batch, out);
}

// round 13
// speedup vs baseline: 1.2760x; 1.2760x over previous
#include <cuda_runtime.h>
#include <cuda_bf16.h>
#include <mma.h>
using namespace nvcuda;

#define NN 50000
#define NE 600000
#define IND 64
#define HID 128
#define NR 10
#define NL 6
#define NG 64

typedef unsigned long long ull;

// ---------------- device scratch (no allocs allowed) ----------------
// g_ob padded by 128 rows: tensor-core GEMM stores full 128-row tiles unguarded.
__device__ float g_h0[NN * HID];
__device__ float g_h1[NN * HID];
__device__ float g_ob[(NN + 128) * HID];
__device__ float g_agg[NN * NR * HID];   // 256 MB: per-node [r][dim] means
__device__ int g_deg[NN];
__device__ int g_off[NN + 1];
__device__ int g_cursor[NN];
__device__ unsigned g_edge[NE];          // (type<<16) | src

// ---------------- packed f32x2 helpers (FFMA2 path, proj GEMM) ----------------
__device__ __forceinline__ ull fma2(ull a, ull b, ull c) {
    ull d;
    asm("fma.rn.f32x2 %0, %1, %2, %3;" : "=l"(d) : "l"(a), "l"(b), "l"(c));
    return d;
}
__device__ __forceinline__ ull dup2(float v) {
    ull d;
    asm("mov.b64 %0, {%1, %1};" : "=l"(d) : "f"(v));
    return d;
}
__device__ __forceinline__ ull pk2(float lo, float hi) {
    ull d;
    asm("mov.b64 %0, {%1, %2};" : "=l"(d) : "f"(lo), "f"(hi));
    return d;
}
__device__ __forceinline__ float2 unpk(ull v) {
    float lo, hi;
    asm("mov.b64 {%0, %1}, %2;" : "=f"(lo), "=f"(hi) : "l"(v));
    return make_float2(lo, hi);
}

// ---------------- CSR build ----------------
__global__ void k_zero_csr() {
    for (int i = blockIdx.x * blockDim.x + threadIdx.x; i < NN;
         i += gridDim.x * blockDim.x) {
        g_deg[i] = 0;
        g_cursor[i] = 0;
    }
}

__global__ void k_count(const int* __restrict__ eidx) {
    int e = blockIdx.x * blockDim.x + threadIdx.x;
    if (e < NE) atomicAdd(&g_deg[eidx[NE + e]], 1);
}

__global__ void k_scan() {
    __shared__ int part[1024];
    const int CH = (NN + 1023) / 1024;  // 49
    int t = threadIdx.x;
    int st = t * CH;
    int s = 0;
    for (int i = 0; i < CH; i++) {
        int idx = st + i;
        if (idx < NN) s += g_deg[idx];
    }
    part[t] = s;
    __syncthreads();
    for (int off = 1; off < 1024; off <<= 1) {
        int v = (t >= off) ? part[t - off] : 0;
        __syncthreads();
        part[t] += v;
        __syncthreads();
    }
    int run = part[t] - s;  // exclusive prefix for this chunk
    for (int i = 0; i < CH; i++) {
        int idx = st + i;
        if (idx < NN) {
            g_off[idx] = run;
            run += g_deg[idx];
        }
    }
    if (t == 1023) g_off[NN] = part[1023];
}

__global__ void k_fill(const int* __restrict__ eidx, const int* __restrict__ et) {
    int e = blockIdx.x * blockDim.x + threadIdx.x;
    if (e < NE) {
        int dst = eidx[NE + e];
        int pos = g_off[dst] + atomicAdd(&g_cursor[dst], 1);
        g_edge[pos] = ((unsigned)et[e] << 16) | (unsigned)eidx[e];
    }
}

// ---------------- scalar SGEMM (used for input projection only) ----------------
__global__ __launch_bounds__(256) void k_gemm(const float* __restrict__ A,
                                              const float* __restrict__ B,
                                              const float* __restrict__ bias,
                                              float* __restrict__ C, int M, int K,
                                              int accum) {
    __shared__ float As[32][132];
    __shared__ float Bs[32][128];
    int tid = threadIdx.x;
    int tx = tid & 15;
    int ty = tid >> 4;
    int row0 = blockIdx.x << 7;

    ull acc[8][4];
#pragma unroll
    for (int m = 0; m < 8; m++)
#pragma unroll
        for (int p = 0; p < 4; p++) acc[m][p] = 0ull;

    for (int k0 = 0; k0 < K; k0 += 32) {
#pragma unroll
        for (int it = 0; it < 4; it++) {
            int id = tid + (it << 8);
            int m = id >> 3;
            int k4 = (id & 7) << 2;
            int gr = row0 + m;
            float4 v = make_float4(0.f, 0.f, 0.f, 0.f);
            if (gr < M) v = *(const float4*)(A + (size_t)gr * K + k0 + k4);
            As[k4 + 0][m] = v.x;
            As[k4 + 1][m] = v.y;
            As[k4 + 2][m] = v.z;
            As[k4 + 3][m] = v.w;
            int kb = id >> 5;
            int n4 = (id & 31) << 2;
            *(float4*)(&Bs[kb][n4]) =
                *(const float4*)(B + (size_t)(k0 + kb) * HID + n4);
        }
        __syncthreads();
#pragma unroll 8
        for (int k = 0; k < 32; k++) {
            float4 a0 = *(const float4*)(&As[k][ty << 3]);
            float4 a1 = *(const float4*)(&As[k][(ty << 3) + 4]);
            float4 b0 = *(const float4*)(&Bs[k][tx << 3]);
            float4 b1 = *(const float4*)(&Bs[k][(tx << 3) + 4]);
            ull bp_[4] = {pk2(b0.x, b0.y), pk2(b0.z, b0.w), pk2(b1.x, b1.y),
                          pk2(b1.z, b1.w)};
            float av[8] = {a0.x, a0.y, a0.z, a0.w, a1.x, a1.y, a1.z, a1.w};
#pragma unroll
            for (int m = 0; m < 8; m++) {
                ull ad = dup2(av[m]);
#pragma unroll
                for (int p = 0; p < 4; p++) acc[m][p] = fma2(ad, bp_[p], acc[m][p]);
            }
        }
        __syncthreads();
    }

#pragma unroll
    for (int m = 0; m < 8; m++) {
        int gr = row0 + (ty << 3) + m;
        if (gr < M) {
            float2* cp = (float2*)(C + (size_t)gr * HID + (tx << 3));
#pragma unroll
            for (int p = 0; p < 4; p++) {
                float2 v = unpk(acc[m][p]);
                if (accum) {
                    float2 o = cp[p];
                    v.x += o.x;
                    v.y += o.y;
                } else if (bias) {
                    v.x += bias[(tx << 3) + 2 * p];
                    v.y += bias[(tx << 3) + 2 * p + 1];
                }
                cp[p] = v;
            }
        }
    }
}

// ------- tensor-core GEMM, bf16 split-precision (hi/lo), fp32 accum ---------
// C[M,128] = A[M,K] @ B[K,128]  (+bias when accum==0 | += C when accum==1)
// 128x128 block tile, BK=32, 512 threads, warp = 32x32 (2x2 wmma frags).
// Split: x = hi + lo (bf16 each); products keep hh + hl + lh (drop ll ~2^-16).
// C-tile rows beyond M land in g_ob's 128-row padding (A loads are zero-guarded).
__global__ __launch_bounds__(512) void k_gemm_tc(const float* __restrict__ A,
                                                 const float* __restrict__ B,
                                                 const float* __restrict__ bias,
                                                 float* __restrict__ C, int M,
                                                 int K, int accum) {
    __shared__ __nv_bfloat16 Ah[128][40];   // 10.0 KB  [m][k], ld=40
    __shared__ __nv_bfloat16 Al[128][40];   // 10.0 KB
    __shared__ __nv_bfloat16 Bh[32][136];   //  8.5 KB  [k][n], ld=136
    __shared__ __nv_bfloat16 Bl[32][136];   //  8.5 KB
    __shared__ float biasT[16][136];        //  8.5 KB (bias broadcast tile)

    int tid = threadIdx.x;
    int wid = tid >> 5;
    int warp_m = (wid & 3) << 5;   // 0,32,64,96
    int warp_n = (wid >> 2) << 5;  // 0,32,64,96
    int row0 = blockIdx.x << 7;

    wmma::fragment<wmma::accumulator, 16, 16, 16, float> c[2][2];

    if (accum) {
#pragma unroll
        for (int i = 0; i < 2; i++)
#pragma unroll
            for (int j = 0; j < 2; j++)
                wmma::load_matrix_sync(
                    c[i][j],
                    C + (size_t)(row0 + warp_m + i * 16) * HID + warp_n + j * 16,
                    HID, wmma::mem_row_major);
    } else {
        for (int idx = tid; idx < 16 * HID; idx += 512) {
            int r = idx >> 7, cn = idx & 127;
            biasT[r][cn] = bias ? bias[cn] : 0.f;
        }
        __syncthreads();
#pragma unroll
        for (int i = 0; i < 2; i++)
#pragma unroll
            for (int j = 0; j < 2; j++)
                wmma::load_matrix_sync(c[i][j], &biasT[0][warp_n + j * 16], 136,
                                       wmma::mem_row_major);
    }

    for (int k0 = 0; k0 < K; k0 += 32) {
#pragma unroll
        for (int it = 0; it < 2; it++) {
            int id = tid + (it << 9);  // 0..1023
            // A tile: 128x32 = 1024 float4
            int m = id >> 3;
            int k4 = (id & 7) << 2;
            int gr = row0 + m;
            float4 v = make_float4(0.f, 0.f, 0.f, 0.f);
            if (gr < M) v = *(const float4*)(A + (size_t)gr * K + k0 + k4);
            {
                __nv_bfloat16 h;
                h = __float2bfloat16(v.x);
                Ah[m][k4 + 0] = h;
                Al[m][k4 + 0] = __float2bfloat16(v.x - __bfloat162float(h));
                h = __float2bfloat16(v.y);
                Ah[m][k4 + 1] = h;
                Al[m][k4 + 1] = __float2bfloat16(v.y - __bfloat162float(h));
                h = __float2bfloat16(v.z);
                Ah[m][k4 + 2] = h;
                Al[m][k4 + 2] = __float2bfloat16(v.z - __bfloat162float(h));
                h = __float2bfloat16(v.w);
                Ah[m][k4 + 3] = h;
                Al[m][k4 + 3] = __float2bfloat16(v.w - __bfloat162float(h));
            }
            // B tile: 32x128 = 1024 float4
            int kb = id >> 5;
            int n4 = (id & 31) << 2;
            float4 b = *(const float4*)(B + (size_t)(k0 + kb) * HID + n4);
            {
                __nv_bfloat16 h;
                h = __float2bfloat16(b.x);
                Bh[kb][n4 + 0] = h;
                Bl[kb][n4 + 0] = __float2bfloat16(b.x - __bfloat162float(h));
                h = __float2bfloat16(b.y);
                Bh[kb][n4 + 1] = h;
                Bl[kb][n4 + 1] = __float2bfloat16(b.y - __bfloat162float(h));
                h = __float2bfloat16(b.z);
                Bh[kb][n4 + 2] = h;
                Bl[kb][n4 + 2] = __float2bfloat16(b.z - __bfloat162float(h));
                h = __float2bfloat16(b.w);
                Bh[kb][n4 + 3] = h;
                Bl[kb][n4 + 3] = __float2bfloat16(b.w - __bfloat162float(h));
            }
        }
        __syncthreads();
#pragma unroll
        for (int kk = 0; kk < 32; kk += 16) {
            wmma::fragment<wmma::matrix_a, 16, 16, 16, __nv_bfloat16,
                           wmma::row_major> ah[2], al[2];
#pragma unroll
            for (int i = 0; i < 2; i++) {
                wmma::load_matrix_sync(ah[i], &Ah[warp_m + i * 16][kk], 40);
                wmma::load_matrix_sync(al[i], &Al[warp_m + i * 16][kk], 40);
            }
#pragma unroll
            for (int j = 0; j < 2; j++) {
                wmma::fragment<wmma::matrix_b, 16, 16, 16, __nv_bfloat16,
                               wmma::row_major> bh, bl;
                wmma::load_matrix_sync(bh, &Bh[kk][warp_n + j * 16], 136);
                wmma::load_matrix_sync(bl, &Bl[kk][warp_n + j * 16], 136);
#pragma unroll
                for (int i = 0; i < 2; i++) {
                    wmma::mma_sync(c[i][j], ah[i], bh, c[i][j]);
                    wmma::mma_sync(c[i][j], ah[i], bl, c[i][j]);
                    wmma::mma_sync(c[i][j], al[i], bh, c[i][j]);
                }
            }
        }
        __syncthreads();
    }

#pragma unroll
    for (int i = 0; i < 2; i++)
#pragma unroll
        for (int j = 0; j < 2; j++)
            wmma::store_matrix_sync(
                C + (size_t)(row0 + warp_m + i * 16) * HID + warp_n + j * 16,
                c[i][j], HID, wmma::mem_row_major);
}

// ---------------- per-node relation-mean aggregation (warp/node) ------------
__global__ __launch_bounds__(256) void k_agg(const float* __restrict__ h) {
    __shared__ float acc[8][NR][HID];  // 40 KB
    __shared__ int cnt[8][NR];
    int w = threadIdx.x >> 5, lane = threadIdx.x & 31;
    int node = (blockIdx.x << 3) + w;  // NN divisible by 8
#pragma unroll
    for (int r = 0; r < NR; r++)
        *(float4*)(&acc[w][r][lane << 2]) = make_float4(0.f, 0.f, 0.f, 0.f);
    if (lane < NR) cnt[w][lane] = 0;
    __syncwarp();

    int beg = g_off[node], end = g_off[node + 1];
    for (int e = beg; e < end; e++) {
        unsigned p = g_edge[e];
        int src = p & 0xFFFF;
        int r = p >> 16;
        float4 v = *(const float4*)(h + ((size_t)src << 7) + (lane << 2));
        float4 a = *(float4*)(&acc[w][r][lane << 2]);
        a.x += v.x;
        a.y += v.y;
        a.z += v.z;
        a.w += v.w;
        *(float4*)(&acc[w][r][lane << 2]) = a;
        if (lane == 0) cnt[w][r]++;
    }
    __syncwarp();

    float* dst = g_agg + (size_t)node * (NR * HID);
#pragma unroll
    for (int r = 0; r < NR; r++) {
        int c = cnt[w][r];
        float s = (c > 0) ? 1.0f / (float)c : 0.0f;
        float4 a = *(float4*)(&acc[w][r][lane << 2]);
        a.x *= s;
        a.y *= s;
        a.z *= s;
        a.w *= s;
        *(float4*)(dst + r * HID + (lane << 2)) = a;
    }
}

// ---------------- LN + relu + residual epilogue (warp/node) ----------------
__global__ __launch_bounds__(256) void k_ln(const float* __restrict__ conv,
                                            const float* __restrict__ hres,
                                            const float* __restrict__ gam,
                                            const float* __restrict__ bet,
                                            float* __restrict__ hout) {
    int w = threadIdx.x >> 5, lane = threadIdx.x & 31;
    int node = (blockIdx.x << 3) + w;
    if (node >= NN) return;
    float4 v = *(const float4*)(conv + ((size_t)node << 7) + (lane << 2));
    float s = v.x + v.y + v.z + v.w;
#pragma unroll
    for (int o = 16; o > 0; o >>= 1) s += __shfl_xor_sync(0xffffffffu, s, o);
    float mu = s * (1.0f / 128.0f);
    float dx = v.x - mu, dy = v.y - mu, dz = v.z - mu, dw = v.w - mu;
    float q = dx * dx + dy * dy + dz * dz + dw * dw;
#pragma unroll
    for (int o = 16; o > 0; o >>= 1) q += __shfl_xor_sync(0xffffffffu, q, o);
    float inv = rsqrtf(q * (1.0f / 128.0f) + 1e-5f);
    float4 g4 = *(const float4*)(gam + (lane << 2));
    float4 b4 = *(const float4*)(bet + (lane << 2));
    float4 r4 = *(const float4*)(hres + ((size_t)node << 7) + (lane << 2));
    float4 o4;
    o4.x = fmaxf(dx * inv * g4.x + b4.x, 0.f) + r4.x;
    o4.y = fmaxf(dy * inv * g4.y + b4.y, 0.f) + r4.y;
    o4.z = fmaxf(dz * inv * g4.z + b4.z, 0.f) + r4.z;
    o4.w = fmaxf(dw * inv * g4.w + b4.w, 0.f) + r4.w;
    *(float4*)(hout + ((size_t)node << 7) + (lane << 2)) = o4;
}

// ---------------- output pooling ----------------
__global__ void k_zero_out(float* out) {
    int i = blockIdx.x * blockDim.x + threadIdx.x;
    if (i < NG * HID) out[i] = 0.f;
}

__global__ void k_pool(const float* __restrict__ h, const int* __restrict__ batch,
                       float* __restrict__ out) {
    int n0 = blockIdx.x * 512;
    if (n0 >= NN) return;
    int d = threadIdx.x;  // 128 threads = dims
    int end = n0 + 512;
    if (end > NN) end = NN;
    int g = batch[n0];
    float s = 0.f;
    for (int n = n0; n < end; n++) {
        int gb = batch[n];
        if (gb != g) {
            atomicAdd(&out[g * HID + d], s);
            s = 0.f;
            g = gb;
        }
        s += h[((size_t)n << 7) + d];
    }
    atomicAdd(&out[g * HID + d], s);
}

// ---------------- launcher ----------------
extern "C" void kernel_launch(void* const* d_in, const int* in_sizes, int n_in,
                              void* d_out, int out_size) {
    const float* x = (const float*)d_in[0];
    const int* eidx = (const int*)d_in[1];
    const int* etype = (const int*)d_in[2];
    const int* batch = (const int*)d_in[3];
    const float* Wp = (const float*)d_in[4];
    const float* bp = (const float*)d_in[5];
    const float* rel_w = (const float*)d_in[6];
    const float* root_w = (const float*)d_in[7];
    const float* conv_b = (const float*)d_in[8];
    const float* ln_g = (const float*)d_in[9];
    const float* ln_b = (const float*)d_in[10];
    float* out = (float*)d_out;

    float *h0, *h1, *ob, *agg;
    cudaGetSymbolAddress((void**)&h0, g_h0);
    cudaGetSymbolAddress((void**)&h1, g_h1);
    cudaGetSymbolAddress((void**)&ob, g_ob);
    cudaGetSymbolAddress((void**)&agg, g_agg);

    const int GB = (NN + 127) / 128;  // 391 tiles (last partially padded)

    // CSR build
    k_zero_csr<<<64, 256>>>();
    k_count<<<(NE + 255) / 256, 256>>>(eidx);
    k_scan<<<1, 1024>>>();
    k_fill<<<(NE + 255) / 256, 256>>>(eidx, etype);

    // input projection: h0 = x @ Wp + bp  (scalar path; only 0.8 GFLOP)
    k_gemm<<<GB, 256>>>(x, Wp, bp, h0, NN, IND, 0);

    float* hc = h0;
    float* hn = h1;
    for (int l = 0; l < NL; l++) {
        k_agg<<<NN / 8, 256>>>(hc);
        k_gemm_tc<<<GB, 512>>>(hc, root_w + (size_t)l * HID * HID,
                               conv_b + (size_t)l * HID, ob, NN, HID, 0);
        k_gemm_tc<<<GB, 512>>>(agg, rel_w + (size_t)l * NR * HID * HID,
                               (const float*)0, ob, NN, NR * HID, 1);
        k_ln<<<NN / 8, 256>>>(ob, hc, ln_g + (size_t)l * HID,
                              ln_b + (size_t)l * HID, hn);
        float* t = hc;
        hc = hn;
        hn = t;
    }

    k_zero_out<<<(NG * HID + 255) / 256, 256>>>(out);
    k_pool<<<(NN + 511) / 512, 128>>>(hc, batch, out);
}

// round 16
// speedup vs baseline: 1.4534x; 1.1390x over previous
#include <cuda_runtime.h>
#include <cuda_bf16.h>
#include <mma.h>
using namespace nvcuda;

#define NN 50000
#define NE 600000
#define IND 64
#define HID 128
#define NR 10
#define NL 6
#define NG 64
#define KREL (NR * HID)

typedef unsigned long long ull;

// ---------------- device scratch (no allocs allowed) ----------------
__device__ float g_h0[NN * HID];
__device__ float g_h1[NN * HID];
__device__ float g_ob[(NN + 128) * HID];        // 128-row pad for unguarded tc tiles
__device__ __nv_bfloat16 g_aggh[NN * KREL];     // split agg means (hi)
__device__ __nv_bfloat16 g_aggl[NN * KREL];     // (lo)
__device__ __nv_bfloat16 g_hh[NN * HID];        // split current h (hi)
__device__ __nv_bfloat16 g_hl[NN * HID];        // (lo)
__device__ __nv_bfloat16 g_wrelh[NL * NR * HID * HID];
__device__ __nv_bfloat16 g_wrell[NL * NR * HID * HID];
__device__ __nv_bfloat16 g_wrooth[NL * HID * HID];
__device__ __nv_bfloat16 g_wrootl[NL * HID * HID];
__device__ int g_deg[NN];
__device__ int g_off[NN + 1];
__device__ int g_cursor[NN];
__device__ unsigned g_edge[NE];                 // (type<<16) | src

// ---------------- packed f32x2 helpers (FFMA2 path, proj GEMM) ----------------
__device__ __forceinline__ ull fma2(ull a, ull b, ull c) {
    ull d;
    asm("fma.rn.f32x2 %0, %1, %2, %3;" : "=l"(d) : "l"(a), "l"(b), "l"(c));
    return d;
}
__device__ __forceinline__ ull dup2(float v) {
    ull d;
    asm("mov.b64 %0, {%1, %1};" : "=l"(d) : "f"(v));
    return d;
}
__device__ __forceinline__ ull pk2(float lo, float hi) {
    ull d;
    asm("mov.b64 %0, {%1, %2};" : "=l"(d) : "f"(lo), "f"(hi));
    return d;
}
__device__ __forceinline__ float2 unpk(ull v) {
    float lo, hi;
    asm("mov.b64 {%0, %1}, %2;" : "=f"(lo), "=f"(hi) : "l"(v));
    return make_float2(lo, hi);
}

// split float4 -> two bf16x2 pairs per plane, stored as 2x4B
__device__ __forceinline__ void split_store4(float4 a, __nv_bfloat16* ph,
                                             __nv_bfloat16* pl) {
    __nv_bfloat16 hx = __float2bfloat16(a.x);
    __nv_bfloat16 hy = __float2bfloat16(a.y);
    __nv_bfloat16 hz = __float2bfloat16(a.z);
    __nv_bfloat16 hw = __float2bfloat16(a.w);
    __nv_bfloat162 h0 = {hx, hy}, h1 = {hz, hw};
    *(__nv_bfloat162*)(ph + 0) = h0;
    *(__nv_bfloat162*)(ph + 2) = h1;
    __nv_bfloat162 l0 = {__float2bfloat16(a.x - __bfloat162float(hx)),
                         __float2bfloat16(a.y - __bfloat162float(hy))};
    __nv_bfloat162 l1 = {__float2bfloat16(a.z - __bfloat162float(hz)),
                         __float2bfloat16(a.w - __bfloat162float(hw))};
    *(__nv_bfloat162*)(pl + 0) = l0;
    *(__nv_bfloat162*)(pl + 2) = l1;
}

// ---------------- elementwise fp32 -> bf16 hi/lo split ----------------
__global__ void k_split(const float* __restrict__ src, __nv_bfloat16* __restrict__ dh,
                        __nv_bfloat16* __restrict__ dl, int n) {
    int i = blockIdx.x * blockDim.x + threadIdx.x;
    if (i < n) {
        float v = src[i];
        __nv_bfloat16 h = __float2bfloat16(v);
        dh[i] = h;
        dl[i] = __float2bfloat16(v - __bfloat162float(h));
    }
}

// ---------------- CSR build ----------------
__global__ void k_zero_csr() {
    for (int i = blockIdx.x * blockDim.x + threadIdx.x; i < NN;
         i += gridDim.x * blockDim.x) {
        g_deg[i] = 0;
        g_cursor[i] = 0;
    }
}

__global__ void k_count(const int* __restrict__ eidx) {
    int e = blockIdx.x * blockDim.x + threadIdx.x;
    if (e < NE) atomicAdd(&g_deg[eidx[NE + e]], 1);
}

__global__ void k_scan() {
    __shared__ int part[1024];
    const int CH = (NN + 1023) / 1024;
    int t = threadIdx.x;
    int st = t * CH;
    int s = 0;
    for (int i = 0; i < CH; i++) {
        int idx = st + i;
        if (idx < NN) s += g_deg[idx];
    }
    part[t] = s;
    __syncthreads();
    for (int off = 1; off < 1024; off <<= 1) {
        int v = (t >= off) ? part[t - off] : 0;
        __syncthreads();
        part[t] += v;
        __syncthreads();
    }
    int run = part[t] - s;
    for (int i = 0; i < CH; i++) {
        int idx = st + i;
        if (idx < NN) {
            g_off[idx] = run;
            run += g_deg[idx];
        }
    }
    if (t == 1023) g_off[NN] = part[1023];
}

__global__ void k_fill(const int* __restrict__ eidx, const int* __restrict__ et) {
    int e = blockIdx.x * blockDim.x + threadIdx.x;
    if (e < NE) {
        int dst = eidx[NE + e];
        int pos = g_off[dst] + atomicAdd(&g_cursor[dst], 1);
        g_edge[pos] = ((unsigned)et[e] << 16) | (unsigned)eidx[e];
    }
}

// ---------------- scalar SGEMM (input projection only) ----------------
__global__ __launch_bounds__(256) void k_gemm(const float* __restrict__ A,
                                              const float* __restrict__ B,
                                              const float* __restrict__ bias,
                                              float* __restrict__ C, int M, int K,
                                              int accum) {
    __shared__ float As[32][132];
    __shared__ float Bs[32][128];
    int tid = threadIdx.x;
    int tx = tid & 15;
    int ty = tid >> 4;
    int row0 = blockIdx.x << 7;

    ull acc[8][4];
#pragma unroll
    for (int m = 0; m < 8; m++)
#pragma unroll
        for (int p = 0; p < 4; p++) acc[m][p] = 0ull;

    for (int k0 = 0; k0 < K; k0 += 32) {
#pragma unroll
        for (int it = 0; it < 4; it++) {
            int id = tid + (it << 8);
            int m = id >> 3;
            int k4 = (id & 7) << 2;
            int gr = row0 + m;
            float4 v = make_float4(0.f, 0.f, 0.f, 0.f);
            if (gr < M) v = *(const float4*)(A + (size_t)gr * K + k0 + k4);
            As[k4 + 0][m] = v.x;
            As[k4 + 1][m] = v.y;
            As[k4 + 2][m] = v.z;
            As[k4 + 3][m] = v.w;
            int kb = id >> 5;
            int n4 = (id & 31) << 2;
            *(float4*)(&Bs[kb][n4]) =
                *(const float4*)(B + (size_t)(k0 + kb) * HID + n4);
        }
        __syncthreads();
#pragma unroll 8
        for (int k = 0; k < 32; k++) {
            float4 a0 = *(const float4*)(&As[k][ty << 3]);
            float4 a1 = *(const float4*)(&As[k][(ty << 3) + 4]);
            float4 b0 = *(const float4*)(&Bs[k][tx << 3]);
            float4 b1 = *(const float4*)(&Bs[k][(tx << 3) + 4]);
            ull bp_[4] = {pk2(b0.x, b0.y), pk2(b0.z, b0.w), pk2(b1.x, b1.y),
                          pk2(b1.z, b1.w)};
            float av[8] = {a0.x, a0.y, a0.z, a0.w, a1.x, a1.y, a1.z, a1.w};
#pragma unroll
            for (int m = 0; m < 8; m++) {
                ull ad = dup2(av[m]);
#pragma unroll
                for (int p = 0; p < 4; p++) acc[m][p] = fma2(ad, bp_[p], acc[m][p]);
            }
        }
        __syncthreads();
    }

#pragma unroll
    for (int m = 0; m < 8; m++) {
        int gr = row0 + (ty << 3) + m;
        if (gr < M) {
            float2* cp = (float2*)(C + (size_t)gr * HID + (tx << 3));
#pragma unroll
            for (int p = 0; p < 4; p++) {
                float2 v = unpk(acc[m][p]);
                if (accum) {
                    float2 o = cp[p];
                    v.x += o.x;
                    v.y += o.y;
                } else if (bias) {
                    v.x += bias[(tx << 3) + 2 * p];
                    v.y += bias[(tx << 3) + 2 * p + 1];
                }
                cp[p] = v;
            }
        }
    }
}

// ------- tensor-core GEMM on PRE-SPLIT bf16 hi/lo planes, fp32 accum --------
// C[M,128] = (Ah+Al)[M,K] @ (Bh+Bl)[K,128], keeping hh + hl + lh terms.
// Tile staging is pure uint2 copies — no conversions in the hot loop.
__global__ __launch_bounds__(512) void k_gemm_tc2(
    const __nv_bfloat16* __restrict__ Ah_, const __nv_bfloat16* __restrict__ Al_,
    const __nv_bfloat16* __restrict__ Bh_, const __nv_bfloat16* __restrict__ Bl_,
    const float* __restrict__ bias, float* __restrict__ C, int M, int K,
    int accum) {
    __shared__ __nv_bfloat16 Ah[128][40];
    __shared__ __nv_bfloat16 Al[128][40];
    __shared__ __nv_bfloat16 Bh[32][136];
    __shared__ __nv_bfloat16 Bl[32][136];
    __shared__ float biasT[16][136];

    int tid = threadIdx.x;
    int wid = tid >> 5;
    int warp_m = (wid & 3) << 5;
    int warp_n = (wid >> 2) << 5;
    int row0 = blockIdx.x << 7;

    wmma::fragment<wmma::accumulator, 16, 16, 16, float> c[2][2];

    if (accum) {
#pragma unroll
        for (int i = 0; i < 2; i++)
#pragma unroll
            for (int j = 0; j < 2; j++)
                wmma::load_matrix_sync(
                    c[i][j],
                    C + (size_t)(row0 + warp_m + i * 16) * HID + warp_n + j * 16,
                    HID, wmma::mem_row_major);
    } else {
        for (int idx = tid; idx < 16 * HID; idx += 512) {
            int r = idx >> 7, cn = idx & 127;
            biasT[r][cn] = bias ? bias[cn] : 0.f;
        }
        __syncthreads();
#pragma unroll
        for (int i = 0; i < 2; i++)
#pragma unroll
            for (int j = 0; j < 2; j++)
                wmma::load_matrix_sync(c[i][j], &biasT[0][warp_n + j * 16], 136,
                                       wmma::mem_row_major);
    }

    const uint2 z2 = make_uint2(0u, 0u);
    for (int k0 = 0; k0 < K; k0 += 32) {
#pragma unroll
        for (int it = 0; it < 2; it++) {
            int id = tid + (it << 9);  // 0..1023
            // A tile: 128x32 bf16 per plane = 1024 uint2 each
            int m = id >> 3;
            int k4 = (id & 7) << 2;
            int gr = row0 + m;
            uint2 vh = z2, vl = z2;
            if (gr < M) {
                vh = *(const uint2*)(Ah_ + (size_t)gr * K + k0 + k4);
                vl = *(const uint2*)(Al_ + (size_t)gr * K + k0 + k4);
            }
            *(uint2*)(&Ah[m][k4]) = vh;
            *(uint2*)(&Al[m][k4]) = vl;
            // B tile: 32x128 bf16 per plane = 1024 uint2 each
            int kb = id >> 5;
            int n4 = (id & 31) << 2;
            *(uint2*)(&Bh[kb][n4]) =
                *(const uint2*)(Bh_ + (size_t)(k0 + kb) * HID + n4);
            *(uint2*)(&Bl[kb][n4]) =
                *(const uint2*)(Bl_ + (size_t)(k0 + kb) * HID + n4);
        }
        __syncthreads();
#pragma unroll
        for (int kk = 0; kk < 32; kk += 16) {
            wmma::fragment<wmma::matrix_a, 16, 16, 16, __nv_bfloat16,
                           wmma::row_major> ah[2], al[2];
#pragma unroll
            for (int i = 0; i < 2; i++) {
                wmma::load_matrix_sync(ah[i], &Ah[warp_m + i * 16][kk], 40);
                wmma::load_matrix_sync(al[i], &Al[warp_m + i * 16][kk], 40);
            }
#pragma unroll
            for (int j = 0; j < 2; j++) {
                wmma::fragment<wmma::matrix_b, 16, 16, 16, __nv_bfloat16,
                               wmma::row_major> bh, bl;
                wmma::load_matrix_sync(bh, &Bh[kk][warp_n + j * 16], 136);
                wmma::load_matrix_sync(bl, &Bl[kk][warp_n + j * 16], 136);
#pragma unroll
                for (int i = 0; i < 2; i++) {
                    wmma::mma_sync(c[i][j], ah[i], bh, c[i][j]);
                    wmma::mma_sync(c[i][j], ah[i], bl, c[i][j]);
                    wmma::mma_sync(c[i][j], al[i], bh, c[i][j]);
                }
            }
        }
        __syncthreads();
    }

#pragma unroll
    for (int i = 0; i < 2; i++)
#pragma unroll
        for (int j = 0; j < 2; j++)
            wmma::store_matrix_sync(
                C + (size_t)(row0 + warp_m + i * 16) * HID + warp_n + j * 16,
                c[i][j], HID, wmma::mem_row_major);
}

// ---- per-node relation-mean aggregation; emits bf16 hi/lo planes -----------
__global__ __launch_bounds__(256) void k_agg(const float* __restrict__ h) {
    __shared__ float acc[8][NR][HID];  // 40 KB
    __shared__ int cnt[8][NR];
    int w = threadIdx.x >> 5, lane = threadIdx.x & 31;
    int node = (blockIdx.x << 3) + w;
#pragma unroll
    for (int r = 0; r < NR; r++)
        *(float4*)(&acc[w][r][lane << 2]) = make_float4(0.f, 0.f, 0.f, 0.f);
    if (lane < NR) cnt[w][lane] = 0;
    __syncwarp();

    int beg = g_off[node], end = g_off[node + 1];
    for (int e = beg; e < end; e++) {
        unsigned p = g_edge[e];
        int src = p & 0xFFFF;
        int r = p >> 16;
        float4 v = *(const float4*)(h + ((size_t)src << 7) + (lane << 2));
        float4 a = *(float4*)(&acc[w][r][lane << 2]);
        a.x += v.x;
        a.y += v.y;
        a.z += v.z;
        a.w += v.w;
        *(float4*)(&acc[w][r][lane << 2]) = a;
        if (lane == 0) cnt[w][r]++;
    }
    __syncwarp();

    __nv_bfloat16* dh = g_aggh + (size_t)node * KREL;
    __nv_bfloat16* dl = g_aggl + (size_t)node * KREL;
#pragma unroll
    for (int r = 0; r < NR; r++) {
        int c = cnt[w][r];
        float s = (c > 0) ? 1.0f / (float)c : 0.0f;
        float4 a = *(float4*)(&acc[w][r][lane << 2]);
        a.x *= s;
        a.y *= s;
        a.z *= s;
        a.w *= s;
        split_store4(a, dh + r * HID + (lane << 2), dl + r * HID + (lane << 2));
    }
}

// ---- LN + relu + residual epilogue; also emits split h for next root-GEMM --
__global__ __launch_bounds__(256) void k_ln(const float* __restrict__ conv,
                                            const float* __restrict__ hres,
                                            const float* __restrict__ gam,
                                            const float* __restrict__ bet,
                                            float* __restrict__ hout) {
    int w = threadIdx.x >> 5, lane = threadIdx.x & 31;
    int node = (blockIdx.x << 3) + w;
    if (node >= NN) return;
    float4 v = *(const float4*)(conv + ((size_t)node << 7) + (lane << 2));
    float s = v.x + v.y + v.z + v.w;
#pragma unroll
    for (int o = 16; o > 0; o >>= 1) s += __shfl_xor_sync(0xffffffffu, s, o);
    float mu = s * (1.0f / 128.0f);
    float dx = v.x - mu, dy = v.y - mu, dz = v.z - mu, dw = v.w - mu;
    float q = dx * dx + dy * dy + dz * dz + dw * dw;
#pragma unroll
    for (int o = 16; o > 0; o >>= 1) q += __shfl_xor_sync(0xffffffffu, q, o);
    float inv = rsqrtf(q * (1.0f / 128.0f) + 1e-5f);
    float4 g4 = *(const float4*)(gam + (lane << 2));
    float4 b4 = *(const float4*)(bet + (lane << 2));
    float4 r4 = *(const float4*)(hres + ((size_t)node << 7) + (lane << 2));
    float4 o4;
    o4.x = fmaxf(dx * inv * g4.x + b4.x, 0.f) + r4.x;
    o4.y = fmaxf(dy * inv * g4.y + b4.y, 0.f) + r4.y;
    o4.z = fmaxf(dz * inv * g4.z + b4.z, 0.f) + r4.z;
    o4.w = fmaxf(dw * inv * g4.w + b4.w, 0.f) + r4.w;
    *(float4*)(hout + ((size_t)node << 7) + (lane << 2)) = o4;
    split_store4(o4, g_hh + ((size_t)node << 7) + (lane << 2),
                 g_hl + ((size_t)node << 7) + (lane << 2));
}

// ---------------- output pooling ----------------
__global__ void k_zero_out(float* out) {
    int i = blockIdx.x * blockDim.x + threadIdx.x;
    if (i < NG * HID) out[i] = 0.f;
}

__global__ void k_pool(const float* __restrict__ h, const int* __restrict__ batch,
                       float* __restrict__ out) {
    int n0 = blockIdx.x * 512;
    if (n0 >= NN) return;
    int d = threadIdx.x;
    int end = n0 + 512;
    if (end > NN) end = NN;
    int g = batch[n0];
    float s = 0.f;
    for (int n = n0; n < end; n++) {
        int gb = batch[n];
        if (gb != g) {
            atomicAdd(&out[g * HID + d], s);
            s = 0.f;
            g = gb;
        }
        s += h[((size_t)n << 7) + d];
    }
    atomicAdd(&out[g * HID + d], s);
}

// ---------------- launcher ----------------
extern "C" void kernel_launch(void* const* d_in, const int* in_sizes, int n_in,
                              void* d_out, int out_size) {
    const float* x = (const float*)d_in[0];
    const int* eidx = (const int*)d_in[1];
    const int* etype = (const int*)d_in[2];
    const int* batch = (const int*)d_in[3];
    const float* Wp = (const float*)d_in[4];
    const float* bp = (const float*)d_in[5];
    const float* rel_w = (const float*)d_in[6];
    const float* root_w = (const float*)d_in[7];
    const float* conv_b = (const float*)d_in[8];
    const float* ln_g = (const float*)d_in[9];
    const float* ln_b = (const float*)d_in[10];
    float* out = (float*)d_out;

    float *h0, *h1, *ob;
    __nv_bfloat16 *aggh, *aggl, *hh, *hl, *wrh, *wrl, *wth, *wtl;
    cudaGetSymbolAddress((void**)&h0, g_h0);
    cudaGetSymbolAddress((void**)&h1, g_h1);
    cudaGetSymbolAddress((void**)&ob, g_ob);
    cudaGetSymbolAddress((void**)&aggh, g_aggh);
    cudaGetSymbolAddress((void**)&aggl, g_aggl);
    cudaGetSymbolAddress((void**)&hh, g_hh);
    cudaGetSymbolAddress((void**)&hl, g_hl);
    cudaGetSymbolAddress((void**)&wrh, g_wrelh);
    cudaGetSymbolAddress((void**)&wrl, g_wrell);
    cudaGetSymbolAddress((void**)&wth, g_wrooth);
    cudaGetSymbolAddress((void**)&wtl, g_wrootl);

    const int GB = (NN + 127) / 128;

    // CSR build
    k_zero_csr<<<64, 256>>>();
    k_count<<<(NE + 255) / 256, 256>>>(eidx);
    k_scan<<<1, 1024>>>();
    k_fill<<<(NE + 255) / 256, 256>>>(eidx, etype);

    // one-time weight splits
    {
        int nrel = NL * NR * HID * HID;
        int nroot = NL * HID * HID;
        k_split<<<(nrel + 255) / 256, 256>>>(rel_w, wrh, wrl, nrel);
        k_split<<<(nroot + 255) / 256, 256>>>(root_w, wth, wtl, nroot);
    }

    // input projection (scalar) + split of h0
    k_gemm<<<GB, 256>>>(x, Wp, bp, h0, NN, IND, 0);
    k_split<<<(NN * HID + 255) / 256, 256>>>(h0, hh, hl, NN * HID);

    float* hc = h0;
    float* hn = h1;
    for (int l = 0; l < NL; l++) {
        k_agg<<<NN / 8, 256>>>(hc);
        k_gemm_tc2<<<GB, 512>>>(hh, hl, wth + (size_t)l * HID * HID,
                                wtl + (size_t)l * HID * HID,
                                conv_b + (size_t)l * HID, ob, NN, HID, 0);
        k_gemm_tc2<<<GB, 512>>>(aggh, aggl, wrh + (size_t)l * NR * HID * HID,
                                wrl + (size_t)l * NR * HID * HID,
                                (const float*)0, ob, NN, KREL, 1);
        k_ln<<<NN / 8, 256>>>(ob, hc, ln_g + (size_t)l * HID,
                              ln_b + (size_t)l * HID, hn);
        float* t = hc;
        hc = hn;
        hn = t;
    }

    k_zero_out<<<(NG * HID + 255) / 256, 256>>>(out);
    k_pool<<<(NN + 511) / 512, 128>>>(hc, batch, out);
}